// round 9
// baseline (speedup 1.0000x reference)
#include <cuda_runtime.h>
#include <cstdint>
#include <float.h>

// Problem constants
#define B_ 8
#define S_ 2048
#define D_ 512
#define Q_ 8
#define C_ 1024
#define T_ (B_*S_)            // 16384 tokens

#define TM 64                 // tokens per CTA (4 m-tiles of 16)
#define NCTA (T_/TM)          // 256
#define NTHREADS 256          // 8 warps = 4 m-tiles x 2 code-halves
#define NKS32 16              // 512 / 32 k-steps
#define NT_ALL 128            // 1024 codes / 8
#define NCHUNK 64             // chunks per q: 8 ng x 8 kc
#define TAU 0.1f
#define QMAX 32512.0f

// smem byte offsets
#define OFF_AHI  0            // [4 mt][16 ks32][32 lane][16B] = 32KB
#define OFF_ALO  32768        // 32KB
#define OFF_B    65536        // 2 x 16KB chunks
#define OFF_CN   98304        // 1024 f32
#define OFF_SB   102400       // 1024 f32 (s_b scale)
#define OFF_SA   106496       // 64 f32
#define OFF_SAI  106752       // 64 f32 (1/s_a)
#define OFF_T3   107008       // [2 nh][4 mt][16 row][6 u32] = 3072B
#define OFF_IDX  110080       // 64 int
#define OFF_NF   110336
#define OFF_NP   110340
#define OFF_FLAG 110344       // 64 int
#define OFF_PM   110600       // 64 int
#define OFF_PC   110856       // 64 int
#define OFF_RB   111112       // 8 f32
#define OFF_RI   111144       // 8 int
#define OFF_LOSS 111176       // 8 f32
#define SMEM_BYTES 111232

__device__ float    g_res[(size_t)T_*D_];                    // 32MB residual
__device__ uint4    g_bfrag8[(size_t)Q_*NT_ALL*NKS32*32];    // 8MB int8 B frags
__device__ float    g_cnorm[Q_*C_];
__device__ float    g_sb[Q_*C_];
__device__ float    g_part[NCTA*Q_];

// ---------------------------------------------------------------------------
__device__ __forceinline__ void cp_async16(unsigned sdst, const void* gsrc) {
    asm volatile("cp.async.cg.shared.global [%0], [%1], 16;" :: "r"(sdst), "l"(gsrc));
}
#define CP_COMMIT() asm volatile("cp.async.commit_group;" ::: "memory")
#define CP_WAIT1()  asm volatile("cp.async.wait_group 1;" ::: "memory")
__device__ __forceinline__ unsigned smem_u32(const void* p) {
    unsigned a;
    asm("{ .reg .u64 t; cvta.to.shared.u64 t, %1; cvt.u32.u64 %0, t; }"
        : "=r"(a) : "l"(p));
    return a;
}
__device__ __forceinline__ void mma_s8(int* c, unsigned a0, unsigned a1,
                                       unsigned a2, unsigned a3,
                                       unsigned b0, unsigned b1) {
    asm("mma.sync.aligned.m16n8k32.row.col.s32.s8.s8.s32 "
        "{%0,%1,%2,%3},{%4,%5,%6,%7},{%8,%9},{%0,%1,%2,%3};"
        : "+r"(c[0]), "+r"(c[1]), "+r"(c[2]), "+r"(c[3])
        : "r"(a0), "r"(a1), "r"(a2), "r"(a3), "r"(b0), "r"(b1));
}
__device__ __forceinline__ unsigned pack4(int a, int b, int c, int d) {
    return (a & 0xFF) | ((b & 0xFF) << 8) | ((c & 0xFF) << 16) | ((d & 0xFF) << 24);
}
// quantize 4 floats -> 16-bit ints -> hi/lo bytes
__device__ __forceinline__ void q4(float4 v, float sinv, int* hi, int* lo) {
    int a[4] = { __float2int_rn(v.x*sinv), __float2int_rn(v.y*sinv),
                 __float2int_rn(v.z*sinv), __float2int_rn(v.w*sinv) };
    #pragma unroll
    for (int i = 0; i < 4; i++) {
        hi[i] = (a[i] + 128) >> 8;
        lo[i] = a[i] - (hi[i] << 8);
    }
}

struct Top3 { float s0, s1, s2; int i0, i1, i2; };
__device__ __forceinline__ void t3_init(Top3& t) {
    t.s0 = t.s1 = t.s2 = FLT_MAX; t.i0 = t.i1 = t.i2 = 0x7fffffff;
}
__device__ __forceinline__ void t3_ins(Top3& t, float s, int i) {
    if (s < t.s2 || (s == t.s2 && i < t.i2)) {
        if (s < t.s1 || (s == t.s1 && i < t.i1)) {
            t.s2 = t.s1; t.i2 = t.i1;
            if (s < t.s0 || (s == t.s0 && i < t.i0)) {
                t.s1 = t.s0; t.i1 = t.i0; t.s0 = s; t.i0 = i;
            } else { t.s1 = s; t.i1 = i; }
        } else { t.s2 = s; t.i2 = i; }
    }
}
__device__ __forceinline__ void t3_shxor(Top3& t, int m) {
    float s0 = __shfl_xor_sync(0xffffffffu, t.s0, m);
    float s1 = __shfl_xor_sync(0xffffffffu, t.s1, m);
    float s2 = __shfl_xor_sync(0xffffffffu, t.s2, m);
    int   i0 = __shfl_xor_sync(0xffffffffu, t.i0, m);
    int   i1 = __shfl_xor_sync(0xffffffffu, t.i1, m);
    int   i2 = __shfl_xor_sync(0xffffffffu, t.i2, m);
    t3_ins(t, s0, i0); t3_ins(t, s1, i1); t3_ins(t, s2, i2);
}

// ---------------------------------------------------------------------------
// Prep: code norms + per-code quantization scales
// ---------------------------------------------------------------------------
__global__ void rvq_prep_norm(const float* __restrict__ cbs) {
    int r = blockIdx.x*blockDim.x + threadIdx.x;
    if (r < Q_*C_) {
        const float4* p = (const float4*)(cbs + (size_t)r*D_);
        float s = 0.f, mx = 1e-30f;
        #pragma unroll 8
        for (int i = 0; i < D_/4; i++) {
            float4 v = p[i];
            s = fmaf(v.x, v.x, s); s = fmaf(v.y, v.y, s);
            s = fmaf(v.z, v.z, s); s = fmaf(v.w, v.w, s);
            mx = fmaxf(mx, fmaxf(fmaxf(fabsf(v.x), fabsf(v.y)),
                                 fmaxf(fabsf(v.z), fabsf(v.w))));
        }
        g_cnorm[r] = s;
        g_sb[r] = mx / QMAX;
    }
}

// Prep: int8 hi/lo B fragments, mma m16n8k32 layout
// g_bfrag8[((q*128 + nt)*16 + ks)*32 + lane] = {bh0, bh1, bl0, bl1}
__global__ void rvq_prep_bfrag8(const float* __restrict__ cbs) {
    int t = blockIdx.x*blockDim.x + threadIdx.x;
    if (t >= Q_*NT_ALL*NKS32*32) return;
    int lane = t & 31;
    int ks   = (t >> 5) & 15;
    int nt   = (t >> 9) & 127;
    int q    = t >> 16;
    int code = nt*8 + (lane >> 2);
    int k0   = ks*32 + (lane & 3)*4;
    const float* cr = cbs + ((size_t)q*C_ + code)*D_;
    float sinv = 1.0f / g_sb[q*C_ + code];
    float4 v0 = *(const float4*)(cr + k0);
    float4 v1 = *(const float4*)(cr + k0 + 16);
    int h0[4], l0[4], h1[4], l1[4];
    q4(v0, sinv, h0, l0);
    q4(v1, sinv, h1, l1);
    g_bfrag8[t] = make_uint4(pack4(h0[0],h0[1],h0[2],h0[3]),
                             pack4(h1[0],h1[1],h1[2],h1[3]),
                             pack4(l0[0],l0[1],l0[2],l0[3]),
                             pack4(l1[0],l1[1],l1[2],l1[3]));
}

// ---------------------------------------------------------------------------
// stage one 16KB B chunk: gidx = q*64 + ng*8 + kc ; [16 ntl][2 ksl][32 lane]x16B
// ---------------------------------------------------------------------------
__device__ __forceinline__ void stage_chunk(int gidx, unsigned sdst, int tid) {
    int q  = gidx >> 6;
    int ng = (gidx >> 3) & 7;
    int kc = gidx & 7;
    #pragma unroll
    for (int j = 0; j < 4; j++) {
        int c   = tid + j*NTHREADS;       // 0..1023 16B units
        int ntl = c >> 6;                 // 0..15
        int ksl = (c >> 5) & 1;
        int ln  = c & 31;
        int half = ntl >> 3, i = ntl & 7;
        const uint4* src = g_bfrag8 +
            ((((size_t)q*NT_ALL + half*64 + ng*8 + i)*NKS32 + kc*2 + ksl)*32 + ln);
        cp_async16(sdst + (c << 4), src);
    }
}

// ---------------------------------------------------------------------------
__global__ __launch_bounds__(NTHREADS, 2)
void rvq_main(const float* __restrict__ x, const float* __restrict__ cbs,
              float* __restrict__ out, int out_size) {
    extern __shared__ char smem[];
    const unsigned sb = smem_u32(smem);
    float* s_cn   = (float*)(smem + OFF_CN);
    float* s_sb   = (float*)(smem + OFF_SB);
    float* s_sa   = (float*)(smem + OFF_SA);
    float* s_sai  = (float*)(smem + OFF_SAI);
    float* s_t3   = (float*)(smem + OFF_T3);
    int*   s_idx  = (int*)(smem + OFF_IDX);
    int*   s_nf   = (int*)(smem + OFF_NF);
    int*   s_np   = (int*)(smem + OFF_NP);
    int*   s_flag = (int*)(smem + OFF_FLAG);
    int*   s_pm   = (int*)(smem + OFF_PM);
    int*   s_pc   = (int*)(smem + OFF_PC);
    float* s_rb   = (float*)(smem + OFF_RB);
    int*   s_ri   = (int*)(smem + OFF_RI);
    float* s_loss = (float*)(smem + OFF_LOSS);

    const int tid  = threadIdx.x;
    const int wid  = tid >> 5;
    const int lane = tid & 31;
    const int mt   = wid & 3;        // m-tile
    const int nh   = wid >> 2;       // code half
    const size_t tok0 = (size_t)blockIdx.x * TM;

    stage_chunk(0, sb + OFF_B, tid);
    CP_COMMIT();

    for (int q = 0; q < Q_; q++) {
        const float* rsrc = q ? (const float*)g_res : x;
        const float* cbq  = cbs + (size_t)q*C_*D_;

        // ---- per-token row max -> s_a scales (warp w: rows w*8..w*8+7) ----
        for (int rr = 0; rr < 8; rr++) {
            int row = wid*8 + rr;
            const float* rp = rsrc + (tok0 + row)*D_;
            float mx = 1e-30f;
            #pragma unroll
            for (int j = 0; j < 16; j++) mx = fmaxf(mx, fabsf(rp[lane + j*32]));
            #pragma unroll
            for (int off = 16; off > 0; off >>= 1)
                mx = fmaxf(mx, __shfl_xor_sync(0xffffffffu, mx, off));
            if (lane == 0) { s_sa[row] = mx / QMAX; s_sai[row] = QMAX / mx; }
        }
        for (int i = tid; i < C_; i += NTHREADS) {
            s_cn[i] = g_cnorm[q*C_ + i];
            s_sb[i] = g_sb[q*C_ + i];
        }
        if (tid == 0) { *s_nf = 0; *s_np = 0; }
        __syncthreads();

        // ---- stage A fragments (int8 hi/lo, mma layout) ----
        #pragma unroll 1
        for (int s = 0; s < 8; s++) {
            int slot = tid + s*NTHREADS;          // [mt][ks32][lane]
            int ln  = slot & 31;
            int ks  = (slot >> 5) & 15;
            int amt = slot >> 9;
            int g   = ln >> 2, tig = ln & 3;
            int r0  = amt*16 + g, r1 = r0 + 8;
            int k0  = ks*32 + tig*4;
            const float* p0 = rsrc + (tok0 + r0)*D_ + k0;
            const float* p1 = rsrc + (tok0 + r1)*D_ + k0;
            float si0 = s_sai[r0], si1 = s_sai[r1];
            float4 v00 = *(const float4*)(p0);
            float4 v01 = *(const float4*)(p0 + 16);
            float4 v10 = *(const float4*)(p1);
            float4 v11 = *(const float4*)(p1 + 16);
            int h[4][4], l[4][4];
            q4(v00, si0, h[0], l[0]);
            q4(v10, si1, h[1], l[1]);
            q4(v01, si0, h[2], l[2]);
            q4(v11, si1, h[3], l[3]);
            *(uint4*)(smem + OFF_AHI + slot*16) =
                make_uint4(pack4(h[0][0],h[0][1],h[0][2],h[0][3]),
                           pack4(h[1][0],h[1][1],h[1][2],h[1][3]),
                           pack4(h[2][0],h[2][1],h[2][2],h[2][3]),
                           pack4(h[3][0],h[3][1],h[3][2],h[3][3]));
            *(uint4*)(smem + OFF_ALO + slot*16) =
                make_uint4(pack4(l[0][0],l[0][1],l[0][2],l[0][3]),
                           pack4(l[1][0],l[1][1],l[1][2],l[1][3]),
                           pack4(l[2][0],l[2][1],l[2][2],l[2][3]),
                           pack4(l[3][0],l[3][1],l[3][2],l[3][3]));
        }
        __syncthreads();

        Top3 t3a, t3b;
        t3_init(t3a); t3_init(t3b);

        for (int ng = 0; ng < 8; ng++) {
            int acc_hh[8][4], acc_m[8][4];
            #pragma unroll
            for (int i = 0; i < 8; i++)
                #pragma unroll
                for (int j = 0; j < 4; j++) { acc_hh[i][j] = 0; acc_m[i][j] = 0; }

            for (int kc = 0; kc < 8; kc++) {
                int gidx = q*NCHUNK + ng*8 + kc;
                if (gidx + 1 < Q_*NCHUNK)
                    stage_chunk(gidx+1, sb + OFF_B + ((gidx+1)&1)*16384, tid);
                CP_COMMIT();
                CP_WAIT1();
                __syncthreads();

                const char* bbase = smem + OFF_B + (gidx&1)*16384 + nh*8192;
                #pragma unroll
                for (int ksl = 0; ksl < 2; ksl++) {
                    int ks32 = kc*2 + ksl;
                    unsigned aoff = (unsigned)(((mt*16 + ks32)*32 + lane)*16);
                    uint4 AH = *(const uint4*)(smem + OFF_AHI + aoff);
                    uint4 AL = *(const uint4*)(smem + OFF_ALO + aoff);
                    #pragma unroll
                    for (int ntl = 0; ntl < 8; ntl++) {
                        uint4 Bv = *(const uint4*)(bbase + ntl*1024 + ksl*512 + lane*16);
                        mma_s8(acc_hh[ntl], AH.x, AH.y, AH.z, AH.w, Bv.x, Bv.y);
                        mma_s8(acc_m [ntl], AH.x, AH.y, AH.z, AH.w, Bv.z, Bv.w);
                        mma_s8(acc_m [ntl], AL.x, AL.y, AL.z, AL.w, Bv.x, Bv.y);
                    }
                }
                __syncthreads();
            }

            // ---- epilogue: scores for this 64-code group (per half) ----
            int ra = mt*16 + (lane >> 2), rb = ra + 8;
            float sa2a = -2.f * s_sa[ra];
            float sa2b = -2.f * s_sa[rb];
            int codebase = nh*512 + ng*64;
            #pragma unroll
            for (int ntl = 0; ntl < 8; ntl++) {
                int n0 = codebase + ntl*8 + (lane & 3)*2;
                float cn0 = s_cn[n0],  cn1 = s_cn[n0+1];
                float sb0 = s_sb[n0],  sb1 = s_sb[n0+1];
                float d00 = fmaf(65536.f, (float)acc_hh[ntl][0], 256.f*(float)acc_m[ntl][0]);
                float d01 = fmaf(65536.f, (float)acc_hh[ntl][1], 256.f*(float)acc_m[ntl][1]);
                float d10 = fmaf(65536.f, (float)acc_hh[ntl][2], 256.f*(float)acc_m[ntl][2]);
                float d11 = fmaf(65536.f, (float)acc_hh[ntl][3], 256.f*(float)acc_m[ntl][3]);
                t3_ins(t3a, fmaf(sa2a*sb0, d00, cn0), n0);
                t3_ins(t3a, fmaf(sa2a*sb1, d01, cn1), n0+1);
                t3_ins(t3b, fmaf(sa2b*sb0, d10, cn0), n0);
                t3_ins(t3b, fmaf(sa2b*sb1, d11, cn1), n0+1);
            }
        }

        // quad merge (4 lanes share each C row)
        t3_shxor(t3a, 1); t3_shxor(t3a, 2);
        t3_shxor(t3b, 1); t3_shxor(t3b, 2);
        if ((lane & 3) == 0) {
            int r = lane >> 2;
            float* e = s_t3 + ((nh*4 + mt)*16 + r)*6;
            e[0] = t3a.s0; e[1] = t3a.s1; e[2] = t3a.s2;
            ((int*)e)[3] = t3a.i0; ((int*)e)[4] = t3a.i1; ((int*)e)[5] = t3a.i2;
            float* f = s_t3 + ((nh*4 + mt)*16 + r + 8)*6;
            f[0] = t3b.s0; f[1] = t3b.s1; f[2] = t3b.s2;
            ((int*)f)[3] = t3b.i0; ((int*)f)[4] = t3b.i1; ((int*)f)[5] = t3b.i2;
        }
        __syncthreads();

        // merge halves + decide (warps 0-3, lanes 0-15)
        if (nh == 0 && lane < 16) {
            const float* e0 = s_t3 + ((0*4 + mt)*16 + lane)*6;
            const float* e1 = s_t3 + ((1*4 + mt)*16 + lane)*6;
            Top3 t;
            t.s0 = e0[0]; t.s1 = e0[1]; t.s2 = e0[2];
            t.i0 = ((const int*)e0)[3]; t.i1 = ((const int*)e0)[4]; t.i2 = ((const int*)e0)[5];
            t3_ins(t, e1[0], ((const int*)e1)[3]);
            t3_ins(t, e1[1], ((const int*)e1)[4]);
            t3_ins(t, e1[2], ((const int*)e1)[5]);
            int token = mt*16 + lane;
            s_idx[token] = t.i0;
            if (t.s2 - t.s0 < TAU) {
                int p = atomicAdd(s_nf, 1);
                s_flag[p] = token;
            } else if (t.s1 - t.s0 < TAU) {
                int p = atomicAdd(s_np, 1);
                s_pm[p] = token; s_pc[p] = t.i1;
            }
        }
        __syncthreads();

        // ---- pair rescore: exact fp32 compare of top-2 (one warp each) ----
        int np = *s_np;
        for (int p = wid; p < np; p += 8) {
            int m = s_pm[p];
            int ca = s_idx[m], cb2 = s_pc[p];
            const float* rr = rsrc + (tok0 + m)*D_;
            const float* pa = cbq + (size_t)ca*D_;
            const float* pb = cbq + (size_t)cb2*D_;
            float da = 0.f, db = 0.f;
            #pragma unroll
            for (int k = 0; k < 16; k++) {
                float rv = rr[lane*16 + k];
                da = fmaf(rv, pa[lane*16 + k], da);
                db = fmaf(rv, pb[lane*16 + k], db);
            }
            #pragma unroll
            for (int off = 16; off > 0; off >>= 1) {
                da += __shfl_down_sync(0xffffffffu, da, off);
                db += __shfl_down_sync(0xffffffffu, db, off);
            }
            if (lane == 0) {
                float sa = fmaf(-2.f, da, s_cn[ca]);
                float sc = fmaf(-2.f, db, s_cn[cb2]);
                int win = (sc < sa || (sc == sa && cb2 < ca)) ? cb2 : ca;
                s_idx[m] = win;
            }
        }
        __syncthreads();

        // ---- full exact rescore (rare) ----
        int nf = *s_nf;
        for (int f = 0; f < nf; f++) {
            int m = s_flag[f];
            const float* rr = rsrc + (tok0 + m)*D_;
            float lb = FLT_MAX; int li = 0x7fffffff;
            #pragma unroll 1
            for (int jj = 0; jj < 4; jj++) {
                int code = wid*128 + jj*32 + lane;
                const float* cr = cbq + (size_t)code*D_;
                float dot = 0.f;
                #pragma unroll 8
                for (int d = 0; d < D_; d++) dot = fmaf(rr[d], cr[d], dot);
                float sc = fmaf(-2.f, dot, s_cn[code]);
                if (sc < lb || (sc == lb && code < li)) { lb = sc; li = code; }
            }
            #pragma unroll
            for (int off = 16; off > 0; off >>= 1) {
                float os = __shfl_down_sync(0xffffffffu, lb, off);
                int   oi = __shfl_down_sync(0xffffffffu, li, off);
                if (os < lb || (os == lb && oi < li)) { lb = os; li = oi; }
            }
            if (lane == 0) { s_rb[wid] = lb; s_ri[wid] = li; }
            __syncthreads();
            if (tid == 0) {
                float fb = FLT_MAX; int fi = 0x7fffffff;
                #pragma unroll
                for (int wv = 0; wv < 8; wv++)
                    if (s_rb[wv] < fb || (s_rb[wv] == fb && s_ri[wv] < fi)) {
                        fb = s_rb[wv]; fi = s_ri[wv];
                    }
                s_idx[m] = fi;
            }
            __syncthreads();
        }

        // ---- residual update + loss + index output ----
        float lloss = 0.f;
        #pragma unroll 1
        for (int i = 0; i < 8; i++) {
            int m = wid*8 + i;
            int idx = s_idx[m];
            const float* cr = cbq + (size_t)idx*D_;
            const float* rr = rsrc + (tok0 + m)*D_;
            float* wr = g_res + (tok0 + m)*D_;
            #pragma unroll
            for (int it = 0; it < 4; it++) {
                int d = it*128 + lane*4;
                float4 rv = *(const float4*)(rr + d);
                float4 cv = *(const float4*)(cr + d);
                float4 nv = make_float4(rv.x-cv.x, rv.y-cv.y, rv.z-cv.z, rv.w-cv.w);
                *(float4*)(wr + d) = nv;
                lloss = fmaf(nv.x, nv.x, lloss);
                lloss = fmaf(nv.y, nv.y, lloss);
                lloss = fmaf(nv.z, nv.z, lloss);
                lloss = fmaf(nv.w, nv.w, lloss);
            }
            if (lane == 0 && out_size >= (int)((long long)T_*D_ + (long long)T_*Q_))
                out[(size_t)T_*D_ + (tok0 + m)*Q_ + q] = (float)idx;
        }
        #pragma unroll
        for (int off = 16; off > 0; off >>= 1)
            lloss += __shfl_down_sync(0xffffffffu, lloss, off);
        if (lane == 0) s_loss[wid] = lloss;
        __syncthreads();
        if (tid == 0) {
            float s = 0.f;
            #pragma unroll
            for (int i = 0; i < 8; i++) s += s_loss[i];
            g_part[blockIdx.x*Q_ + q] = s;
        }
        __syncthreads();   // residual visible before next q's row-max/staging
    }

    // quantized_out = x - residual_final
    for (int i = tid; i < TM*(D_/4); i += NTHREADS) {
        int row = i >> 7, c4 = i & 127;
        float4 xv = ((const float4*)(x + (tok0+row)*D_))[c4];
        float4 rv = ((const float4*)(g_res + (tok0+row)*D_))[c4];
        ((float4*)(out + (tok0+row)*D_))[c4] =
            make_float4(xv.x-rv.x, xv.y-rv.y, xv.z-rv.z, xv.w-rv.w);
    }
}

// ---------------------------------------------------------------------------
__global__ void rvq_fin(float* __restrict__ out, int out_size) {
    int q = threadIdx.x;
    if (q < Q_ && out_size >= (int)((long long)T_*D_ + (long long)T_*Q_ + Q_)) {
        float s = 0.f;
        for (int c = 0; c < NCTA; c++) s += g_part[c*Q_ + q];
        out[(size_t)T_*D_ + (size_t)T_*Q_ + q] = s / (float)((long long)T_*D_);
    }
}

// ---------------------------------------------------------------------------
extern "C" void kernel_launch(void* const* d_in, const int* in_sizes, int n_in,
                              void* d_out, int out_size) {
    const float* x;
    const float* cbs;
    if (in_sizes[0] == T_*D_) { x = (const float*)d_in[0]; cbs = (const float*)d_in[1]; }
    else                      { x = (const float*)d_in[1]; cbs = (const float*)d_in[0]; }
    float* out = (float*)d_out;

    cudaFuncSetAttribute(rvq_main,
                         cudaFuncAttributeMaxDynamicSharedMemorySize, SMEM_BYTES);

    rvq_prep_norm<<<(Q_*C_ + 255)/256, 256>>>(cbs);
    rvq_prep_bfrag8<<<(Q_*NT_ALL*NKS32*32)/256, 256>>>(cbs);
    rvq_main<<<NCTA, NTHREADS, SMEM_BYTES>>>(x, cbs, out, out_size);
    rvq_fin<<<1, 32>>>(out, out_size);
}

// round 10
// speedup vs baseline: 3.6983x; 3.6983x over previous
#include <cuda_runtime.h>
#include <cuda_fp16.h>
#include <cstdint>
#include <float.h>

// Problem constants
#define B_ 8
#define S_ 2048
#define D_ 512
#define Q_ 8
#define C_ 1024
#define T_ (B_*S_)            // 16384 tokens

#define TM 64                 // tokens per CTA (4 m-tiles of 16)
#define NCTA (T_/TM)          // 256
#define NTHREADS 256          // 8 warps = 4 m-tiles x 2 code-halves
#define NKS 32                // 512 / 16 k-steps
#define NT_ALL 128            // 1024 codes / 8
#define TAU 0.1f

// smem byte offsets
#define OFF_AHI  0            // [4 mt][32 ks][32 lane][16B] = 64KB
#define OFF_ALO  65536        // 64KB
#define OFF_B    131072       // 2 x 16KB chunks (fp16 hi only)
#define OFF_CN   163840       // 1024 f32
#define OFF_T3   167936       // [2 nh][4 mt][16 row][6 u32] = 3072B
#define OFF_IDX  171008       // 64 int
#define OFF_NF   171264
#define OFF_NP   171268
#define OFF_FLAG 171272       // 64 int
#define OFF_PM   171528       // 64 int
#define OFF_PC   171784       // 64 int
#define OFF_RB   172040       // 8 f32
#define OFF_RI   172072       // 8 int
#define OFF_LOSS 172104       // 8 f32
#define SMEM_BYTES 172160

__device__ float  g_res[(size_t)T_*D_];                // 32MB residual
__device__ uint2  g_bfrag[(size_t)Q_*NT_ALL*NKS*32];   // 8MB fp16-hi B frags
__device__ float  g_cnorm[Q_*C_];
__device__ float  g_part[NCTA*Q_];

// ---------------------------------------------------------------------------
__device__ __forceinline__ void cp_async16(unsigned sdst, const void* gsrc) {
    asm volatile("cp.async.cg.shared.global [%0], [%1], 16;" :: "r"(sdst), "l"(gsrc));
}
#define CP_COMMIT() asm volatile("cp.async.commit_group;" ::: "memory")
#define CP_WAIT1()  asm volatile("cp.async.wait_group 1;" ::: "memory")
__device__ __forceinline__ unsigned smem_u32(const void* p) {
    unsigned a;
    asm("{ .reg .u64 t; cvta.to.shared.u64 t, %1; cvt.u32.u64 %0, t; }"
        : "=r"(a) : "l"(p));
    return a;
}
__device__ __forceinline__ void mma_f16(float* c, unsigned a0, unsigned a1,
                                        unsigned a2, unsigned a3,
                                        unsigned b0, unsigned b1) {
    asm("mma.sync.aligned.m16n8k16.row.col.f32.f16.f16.f32 "
        "{%0,%1,%2,%3},{%4,%5,%6,%7},{%8,%9},{%0,%1,%2,%3};"
        : "+f"(c[0]), "+f"(c[1]), "+f"(c[2]), "+f"(c[3])
        : "r"(a0), "r"(a1), "r"(a2), "r"(a3), "r"(b0), "r"(b1));
}
// fp16 hi/lo split of two floats; returns packed hi, writes packed lo
__device__ __forceinline__ unsigned pack_hilo(float x0, float x1, unsigned& lo) {
    __half h0 = __float2half_rn(x0);
    __half h1 = __float2half_rn(x1);
    __half l0 = __float2half_rn(x0 - __half2float(h0));
    __half l1 = __float2half_rn(x1 - __half2float(h1));
    lo = (unsigned)__half_as_ushort(l0) | ((unsigned)__half_as_ushort(l1) << 16);
    return (unsigned)__half_as_ushort(h0) | ((unsigned)__half_as_ushort(h1) << 16);
}
__device__ __forceinline__ unsigned pack_hi(float x0, float x1) {
    __half h0 = __float2half_rn(x0);
    __half h1 = __float2half_rn(x1);
    return (unsigned)__half_as_ushort(h0) | ((unsigned)__half_as_ushort(h1) << 16);
}

struct Top3 { float s0, s1, s2; int i0, i1, i2; };
__device__ __forceinline__ void t3_init(Top3& t) {
    t.s0 = t.s1 = t.s2 = FLT_MAX; t.i0 = t.i1 = t.i2 = 0x7fffffff;
}
__device__ __forceinline__ void t3_ins(Top3& t, float s, int i) {
    if (s < t.s2 || (s == t.s2 && i < t.i2)) {
        if (s < t.s1 || (s == t.s1 && i < t.i1)) {
            t.s2 = t.s1; t.i2 = t.i1;
            if (s < t.s0 || (s == t.s0 && i < t.i0)) {
                t.s1 = t.s0; t.i1 = t.i0; t.s0 = s; t.i0 = i;
            } else { t.s1 = s; t.i1 = i; }
        } else { t.s2 = s; t.i2 = i; }
    }
}
__device__ __forceinline__ void t3_shxor(Top3& t, int m) {
    float s0 = __shfl_xor_sync(0xffffffffu, t.s0, m);
    float s1 = __shfl_xor_sync(0xffffffffu, t.s1, m);
    float s2 = __shfl_xor_sync(0xffffffffu, t.s2, m);
    int   i0 = __shfl_xor_sync(0xffffffffu, t.i0, m);
    int   i1 = __shfl_xor_sync(0xffffffffu, t.i1, m);
    int   i2 = __shfl_xor_sync(0xffffffffu, t.i2, m);
    t3_ins(t, s0, i0); t3_ins(t, s1, i1); t3_ins(t, s2, i2);
}

// ---------------------------------------------------------------------------
// Prep: code norms
// ---------------------------------------------------------------------------
__global__ void rvq_prep_norm(const float* __restrict__ cbs) {
    int r = blockIdx.x*blockDim.x + threadIdx.x;
    if (r < Q_*C_) {
        const float4* p = (const float4*)(cbs + (size_t)r*D_);
        float s = 0.f;
        #pragma unroll 8
        for (int i = 0; i < D_/4; i++) {
            float4 v = p[i];
            s = fmaf(v.x, v.x, s); s = fmaf(v.y, v.y, s);
            s = fmaf(v.z, v.z, s); s = fmaf(v.w, v.w, s);
        }
        g_cnorm[r] = s;
    }
}

// Prep: B fragments (fp16 hi only) in mma order: [q][nt][ks][lane]{bh0,bh1}
__global__ void rvq_prep_bfrag(const float* __restrict__ cbs) {
    int t = blockIdx.x*blockDim.x + threadIdx.x;
    if (t >= Q_*NT_ALL*NKS*32) return;
    int lane = t & 31;
    int ks   = (t >> 5) & 31;
    int nt   = (t >> 10) & 127;
    int q    = t >> 17;
    int code = nt*8 + (lane >> 2);
    int k0   = ks*16 + (lane & 3)*2;
    const float* cr = cbs + ((size_t)q*C_ + code)*D_;
    float2 v0 = *(const float2*)(cr + k0);
    float2 v1 = *(const float2*)(cr + k0 + 8);
    g_bfrag[t] = make_uint2(pack_hi(v0.x, v0.y), pack_hi(v1.x, v1.y));
}

// ---------------------------------------------------------------------------
// stage one 16KB B chunk (ng,kc): [16 ntl][4 ksl][32 lane] x 8B
// ---------------------------------------------------------------------------
__device__ __forceinline__ void stage_chunk(int q, int idx, unsigned sdst, int tid) {
    int ng = idx >> 3, kc = idx & 7;
    #pragma unroll
    for (int j = 0; j < 4; j++) {
        int c    = tid + j*NTHREADS;       // 0..1023 16B units (2 lane-items)
        int ntl  = c >> 6;                 // 0..15
        int ksl  = (c >> 4) & 3;
        int lnp  = c & 15;                 // lane pair
        int half = ntl >> 3, i = ntl & 7;
        int nt   = half*64 + ng*8 + i;
        const uint2* src = g_bfrag +
            ((((size_t)q*NT_ALL + nt)*NKS + kc*4 + ksl)*32 + lnp*2);
        cp_async16(sdst + (c << 4), src);
    }
}

// ---------------------------------------------------------------------------
__global__ __launch_bounds__(NTHREADS, 1)
void rvq_main(const float* __restrict__ x, const float* __restrict__ cbs,
              float* __restrict__ out, int out_size) {
    extern __shared__ char smem[];
    const unsigned sb = smem_u32(smem);
    float* s_cn   = (float*)(smem + OFF_CN);
    float* s_t3   = (float*)(smem + OFF_T3);
    int*   s_idx  = (int*)(smem + OFF_IDX);
    int*   s_nf   = (int*)(smem + OFF_NF);
    int*   s_np   = (int*)(smem + OFF_NP);
    int*   s_flag = (int*)(smem + OFF_FLAG);
    int*   s_pm   = (int*)(smem + OFF_PM);
    int*   s_pc   = (int*)(smem + OFF_PC);
    float* s_rb   = (float*)(smem + OFF_RB);
    int*   s_ri   = (int*)(smem + OFF_RI);
    float* s_loss = (float*)(smem + OFF_LOSS);

    const int tid  = threadIdx.x;
    const int wid  = tid >> 5;
    const int lane = tid & 31;
    const int mt   = wid & 3;        // m-tile
    const int nh   = wid >> 2;       // code half
    const size_t tok0 = (size_t)blockIdx.x * TM;

    for (int q = 0; q < Q_; q++) {
        const float* rsrc = q ? (const float*)g_res : x;
        const float* cbq  = cbs + (size_t)q*C_*D_;

        // ---- stage A fragments (fp16 hi/lo) + cnorm ----
        #pragma unroll 1
        for (int s = 0; s < 16; s++) {
            int slot = tid + s*NTHREADS;           // (mt,ks,lane)
            int smt = slot >> 10, sks = (slot >> 5) & 31, sls = slot & 31;
            int rowa = smt*16 + (sls >> 2);
            int k0 = sks*16 + (sls & 3)*2;
            const float* rp = rsrc + (tok0 + rowa)*D_ + k0;
            float2 v0 = *(const float2*)(rp);
            float2 v1 = *(const float2*)(rp + 8*D_);
            float2 v2 = *(const float2*)(rp + 8);
            float2 v3 = *(const float2*)(rp + 8*D_ + 8);
            unsigned l0, l1, l2, l3;
            unsigned h0 = pack_hilo(v0.x, v0.y, l0);
            unsigned h1 = pack_hilo(v1.x, v1.y, l1);
            unsigned h2 = pack_hilo(v2.x, v2.y, l2);
            unsigned h3 = pack_hilo(v3.x, v3.y, l3);
            *(uint4*)(smem + OFF_AHI + slot*16) = make_uint4(h0, h1, h2, h3);
            *(uint4*)(smem + OFF_ALO + slot*16) = make_uint4(l0, l1, l2, l3);
        }
        for (int i = tid; i < C_; i += NTHREADS) s_cn[i] = g_cnorm[q*C_ + i];
        if (tid == 0) { *s_nf = 0; *s_np = 0; }
        __syncthreads();

        stage_chunk(q, 0, sb + OFF_B, tid);
        CP_COMMIT();

        Top3 t3a, t3b;
        t3_init(t3a); t3_init(t3b);

        for (int ng = 0; ng < 8; ng++) {
            float acc[8][4];
            #pragma unroll
            for (int i = 0; i < 8; i++)
                #pragma unroll
                for (int j = 0; j < 4; j++) acc[i][j] = 0.f;

            for (int kc = 0; kc < 8; kc++) {
                int idx = ng*8 + kc;
                if (idx + 1 < 64)
                    stage_chunk(q, idx+1, sb + OFF_B + ((idx+1)&1)*16384, tid);
                CP_COMMIT();
                CP_WAIT1();
                __syncthreads();

                const char* bbase = smem + OFF_B + (idx&1)*16384 + nh*8192;
                #pragma unroll
                for (int ksl = 0; ksl < 4; ksl++) {
                    int ks = kc*4 + ksl;
                    unsigned aoff = (unsigned)(((mt*32 + ks)*32 + lane)*16);
                    uint4 AH = *(const uint4*)(smem + OFF_AHI + aoff);
                    uint4 AL = *(const uint4*)(smem + OFF_ALO + aoff);
                    #pragma unroll
                    for (int ntl = 0; ntl < 8; ntl++) {
                        uint2 Bv = *(const uint2*)(bbase + ntl*1024 + ksl*256 + lane*8);
                        mma_f16(acc[ntl], AH.x, AH.y, AH.z, AH.w, Bv.x, Bv.y);
                        mma_f16(acc[ntl], AL.x, AL.y, AL.z, AL.w, Bv.x, Bv.y);
                    }
                }
                __syncthreads();
            }

            // epilogue: scores for this 64-code group
            int codebase = nh*512 + ng*64;
            #pragma unroll
            for (int ntl = 0; ntl < 8; ntl++) {
                int n0 = codebase + ntl*8 + (lane & 3)*2;
                float cn0 = s_cn[n0], cn1 = s_cn[n0+1];
                t3_ins(t3a, fmaf(-2.f, acc[ntl][0], cn0), n0);
                t3_ins(t3a, fmaf(-2.f, acc[ntl][1], cn1), n0+1);
                t3_ins(t3b, fmaf(-2.f, acc[ntl][2], cn0), n0);
                t3_ins(t3b, fmaf(-2.f, acc[ntl][3], cn1), n0+1);
            }
        }

        // quad merge (4 lanes share each C row)
        t3_shxor(t3a, 1); t3_shxor(t3a, 2);
        t3_shxor(t3b, 1); t3_shxor(t3b, 2);
        if ((lane & 3) == 0) {
            int r = lane >> 2;
            float* e = s_t3 + ((nh*4 + mt)*16 + r)*6;
            e[0] = t3a.s0; e[1] = t3a.s1; e[2] = t3a.s2;
            ((int*)e)[3] = t3a.i0; ((int*)e)[4] = t3a.i1; ((int*)e)[5] = t3a.i2;
            float* f = s_t3 + ((nh*4 + mt)*16 + r + 8)*6;
            f[0] = t3b.s0; f[1] = t3b.s1; f[2] = t3b.s2;
            ((int*)f)[3] = t3b.i0; ((int*)f)[4] = t3b.i1; ((int*)f)[5] = t3b.i2;
        }
        __syncthreads();

        // merge halves + decide (warps 0-3, lanes 0-15)
        if (nh == 0 && lane < 16) {
            const float* e0 = s_t3 + ((0*4 + mt)*16 + lane)*6;
            const float* e1 = s_t3 + ((1*4 + mt)*16 + lane)*6;
            Top3 t;
            t.s0 = e0[0]; t.s1 = e0[1]; t.s2 = e0[2];
            t.i0 = ((const int*)e0)[3]; t.i1 = ((const int*)e0)[4]; t.i2 = ((const int*)e0)[5];
            t3_ins(t, e1[0], ((const int*)e1)[3]);
            t3_ins(t, e1[1], ((const int*)e1)[4]);
            t3_ins(t, e1[2], ((const int*)e1)[5]);
            int token = mt*16 + lane;
            s_idx[token] = t.i0;
            if (t.s2 - t.s0 < TAU) {
                int p = atomicAdd(s_nf, 1);
                s_flag[p] = token;
            } else if (t.s1 - t.s0 < TAU) {
                int p = atomicAdd(s_np, 1);
                s_pm[p] = token; s_pc[p] = t.i1;
            }
        }
        __syncthreads();

        // ---- pair rescore: exact fp32 compare of top-2 (one warp each) ----
        int np = *s_np;
        for (int p = wid; p < np; p += 8) {
            int m = s_pm[p];
            int ca = s_idx[m], cb2 = s_pc[p];
            const float* rr = rsrc + (tok0 + m)*D_;
            const float* pa = cbq + (size_t)ca*D_;
            const float* pb = cbq + (size_t)cb2*D_;
            float da = 0.f, db = 0.f;
            #pragma unroll
            for (int k = 0; k < 16; k++) {
                float rv = rr[lane*16 + k];
                da = fmaf(rv, pa[lane*16 + k], da);
                db = fmaf(rv, pb[lane*16 + k], db);
            }
            #pragma unroll
            for (int off = 16; off > 0; off >>= 1) {
                da += __shfl_down_sync(0xffffffffu, da, off);
                db += __shfl_down_sync(0xffffffffu, db, off);
            }
            if (lane == 0) {
                float sa = fmaf(-2.f, da, s_cn[ca]);
                float sc = fmaf(-2.f, db, s_cn[cb2]);
                int win = (sc < sa || (sc == sa && cb2 < ca)) ? cb2 : ca;
                s_idx[m] = win;
            }
        }
        __syncthreads();

        // ---- full exact rescore (rare) ----
        int nf = *s_nf;
        for (int f = 0; f < nf; f++) {
            int m = s_flag[f];
            const float* rr = rsrc + (tok0 + m)*D_;
            float lb = FLT_MAX; int li = 0x7fffffff;
            #pragma unroll 1
            for (int jj = 0; jj < 4; jj++) {
                int code = wid*128 + jj*32 + lane;
                const float* cr = cbq + (size_t)code*D_;
                float dot = 0.f;
                #pragma unroll 8
                for (int d = 0; d < D_; d++) dot = fmaf(rr[d], cr[d], dot);
                float sc = fmaf(-2.f, dot, s_cn[code]);
                if (sc < lb || (sc == lb && code < li)) { lb = sc; li = code; }
            }
            #pragma unroll
            for (int off = 16; off > 0; off >>= 1) {
                float os = __shfl_down_sync(0xffffffffu, lb, off);
                int   oi = __shfl_down_sync(0xffffffffu, li, off);
                if (os < lb || (os == lb && oi < li)) { lb = os; li = oi; }
            }
            if (lane == 0) { s_rb[wid] = lb; s_ri[wid] = li; }
            __syncthreads();
            if (tid == 0) {
                float fb = FLT_MAX; int fi = 0x7fffffff;
                #pragma unroll
                for (int wv = 0; wv < 8; wv++)
                    if (s_rb[wv] < fb || (s_rb[wv] == fb && s_ri[wv] < fi)) {
                        fb = s_rb[wv]; fi = s_ri[wv];
                    }
                s_idx[m] = fi;
            }
            __syncthreads();
        }

        // ---- residual update + loss + index output ----
        float lloss = 0.f;
        #pragma unroll 1
        for (int i = 0; i < 8; i++) {
            int m = wid*8 + i;
            int idx = s_idx[m];
            const float* cr = cbq + (size_t)idx*D_;
            const float* rr = rsrc + (tok0 + m)*D_;
            float* wr = g_res + (tok0 + m)*D_;
            #pragma unroll
            for (int it = 0; it < 4; it++) {
                int d = it*128 + lane*4;
                float4 rv = *(const float4*)(rr + d);
                float4 cv = *(const float4*)(cr + d);
                float4 nv = make_float4(rv.x-cv.x, rv.y-cv.y, rv.z-cv.z, rv.w-cv.w);
                *(float4*)(wr + d) = nv;
                lloss = fmaf(nv.x, nv.x, lloss);
                lloss = fmaf(nv.y, nv.y, lloss);
                lloss = fmaf(nv.z, nv.z, lloss);
                lloss = fmaf(nv.w, nv.w, lloss);
            }
            if (lane == 0 && out_size >= (int)((long long)T_*D_ + (long long)T_*Q_))
                out[(size_t)T_*D_ + (tok0 + m)*Q_ + q] = (float)idx;
        }
        #pragma unroll
        for (int off = 16; off > 0; off >>= 1)
            lloss += __shfl_down_sync(0xffffffffu, lloss, off);
        if (lane == 0) s_loss[wid] = lloss;
        __syncthreads();
        if (tid == 0) {
            float s = 0.f;
            #pragma unroll
            for (int i = 0; i < 8; i++) s += s_loss[i];
            g_part[blockIdx.x*Q_ + q] = s;
        }
        __syncthreads();   // residual visible before next q's staging
    }

    // quantized_out = x - residual_final
    for (int i = tid; i < TM*(D_/4); i += NTHREADS) {
        int row = i >> 7, c4 = i & 127;
        float4 xv = ((const float4*)(x + (tok0+row)*D_))[c4];
        float4 rv = ((const float4*)(g_res + (tok0+row)*D_))[c4];
        ((float4*)(out + (tok0+row)*D_))[c4] =
            make_float4(xv.x-rv.x, xv.y-rv.y, xv.z-rv.z, xv.w-rv.w);
    }
}

// ---------------------------------------------------------------------------
__global__ void rvq_fin(float* __restrict__ out, int out_size) {
    int q = threadIdx.x;
    if (q < Q_ && out_size >= (int)((long long)T_*D_ + (long long)T_*Q_ + Q_)) {
        float s = 0.f;
        for (int c = 0; c < NCTA; c++) s += g_part[c*Q_ + q];
        out[(size_t)T_*D_ + (size_t)T_*Q_ + q] = s / (float)((long long)T_*D_);
    }
}

// ---------------------------------------------------------------------------
extern "C" void kernel_launch(void* const* d_in, const int* in_sizes, int n_in,
                              void* d_out, int out_size) {
    const float* x;
    const float* cbs;
    if (in_sizes[0] == T_*D_) { x = (const float*)d_in[0]; cbs = (const float*)d_in[1]; }
    else                      { x = (const float*)d_in[1]; cbs = (const float*)d_in[0]; }
    float* out = (float*)d_out;

    cudaFuncSetAttribute(rvq_main,
                         cudaFuncAttributeMaxDynamicSharedMemorySize, SMEM_BYTES);

    rvq_prep_norm<<<(Q_*C_ + 255)/256, 256>>>(cbs);
    rvq_prep_bfrag<<<(Q_*NT_ALL*NKS*32)/256, 256>>>(cbs);
    rvq_main<<<NCTA, NTHREADS, SMEM_BYTES>>>(x, cbs, out, out_size);
    rvq_fin<<<1, 32>>>(out, out_size);
}